// round 8
// baseline (speedup 1.0000x reference)
#include <cuda_runtime.h>
#include <cstdint>

#define BB 2048
#define NN 512
#define UU 64
#define NT 512            // threads per CTA (16 warps)
#define NCTA 296          // 2 CTAs per SM on 148 SMs

#define TILE_F (256 * 64) // half-batch tile: rows 0..255 (64 KB)
// tile + arrA + arrB + rpart + scratch + knp
#define SMEM_FLOATS (TILE_F + NN + NN + 2048 + 16 + 8)

// ---- block reductions (512 threads, 16 warps) ----
__device__ __forceinline__ float blockReduceSum(float v, float* scratch) {
    #pragma unroll
    for (int o = 16; o; o >>= 1) v += __shfl_xor_sync(0xffffffffu, v, o);
    int w = threadIdx.x >> 5, l = threadIdx.x & 31;
    if (l == 0) scratch[w] = v;
    __syncthreads();
    if (threadIdx.x < 16) {
        v = scratch[threadIdx.x];
        #pragma unroll
        for (int o = 8; o; o >>= 1) v += __shfl_xor_sync(0x0000ffffu, v, o);
        if (threadIdx.x == 0) scratch[0] = v;
    }
    __syncthreads();
    return scratch[0];   // scratch rewritten only after a later barrier
}

__device__ __forceinline__ void stg_cs(float* p, float4 v) {
    asm volatile("st.global.cs.v4.f32 [%0], {%1, %2, %3, %4};"
                 :: "l"(p), "f"(v.x), "f"(v.y), "f"(v.z), "f"(v.w) : "memory");
}

__global__ __launch_bounds__(NT, 2) void ntm_kernel(
    const float* __restrict__ memory, const float* __restrict__ k,
    const float* __restrict__ beta_p, const float* __restrict__ g_p,
    const float* __restrict__ s,      const float* __restrict__ gamma_p,
    const float* __restrict__ w_pre,  const float* __restrict__ e,
    const float* __restrict__ a,
    float* __restrict__ out_w, float* __restrict__ out_r, float* __restrict__ out_m)
{
    extern __shared__ float dyn[];
    float* tile    = dyn;                  // 16384: rows 0..255
    float* arrA    = dyn + TILE_F;         // 512: sims -> final w
    float* arrB    = arrA + NN;            // 512: gated weights / r stage-2
    float* rpart   = arrB + NN;            // 2048
    float* scratch = rpart + 2048;         // 16
    float* knp     = scratch + 16;         // 1: 1/||k||

    const int tid  = threadIdx.x;
    const int gid  = tid >> 4;             // 0..31
    const int gl   = tid & 15;
    const int warp = tid >> 5;
    const int lane = tid & 31;

    const float beta  = beta_p[0];
    const float gg    = g_p[0];
    const float gamma = gamma_p[0];

    for (int b = blockIdx.x; b < BB; b += NCTA) {
        const float* memb  = memory + ((long)b << 15);
        float*       outmb = out_m  + ((long)b << 15);

        // ---- k: per-thread direct load; 1/||k|| on warp 0 ----
        const float4 k4 = *(const float4*)(k + b * UU + gl * 4);
        if (warp == 0) {
            float kv0 = k[b * UU + lane];
            float kv1 = k[b * UU + 32 + lane];
            float kq = kv0 * kv0 + kv1 * kv1;
            #pragma unroll
            for (int o = 16; o; o >>= 1) kq += __shfl_xor_sync(0xffffffffu, kq, o);
            if (lane == 0) knp[0] = 1.f / fmaxf(sqrtf(kq), 1e-8f);
        }

        // ---- phase 1: load rows, sims; rows<256 also cached into smem tile ----
        // group gid owns rows gid + 32*i; i<8 -> tile, i>=8 -> L2 re-read later
        #pragma unroll 4
        for (int i = 0; i < 16; ++i) {
            int row = gid + (i << 5);
            float4 m = *(const float4*)(memb + row * 64 + gl * 4);
            if (i < 8) *(float4*)(tile + row * 64 + gl * 4) = m;
            float d = m.x * k4.x + m.y * k4.y + m.z * k4.z + m.w * k4.w;
            float q = m.x * m.x + m.y * m.y + m.z * m.z + m.w * m.w;
            #pragma unroll
            for (int o = 8; o; o >>= 1) {
                d += __shfl_xor_sync(0xffffffffu, d, o);
                q += __shfl_xor_sync(0xffffffffu, q, o);
            }
            if (gl == 0) arrA[row] = d / fmaxf(sqrtf(q), 1e-8f);  // ny deferred
        }
        __syncthreads();                   // publish arrA + knp

        // ---- phase 2: softmax (no max-sub: |beta*sim| <= 5), gate, shift, sharpen ----
        const float bn = beta * knp[0];
        float e0 = expf(bn * arrA[tid]);
        float esum = blockReduceSum(e0, scratch);
        arrB[tid] = gg * e0 / esum + (1.f - gg) * w_pre[b * NN + tid];
        __syncthreads();                   // publish arrB

        const float s0 = s[b * 3 + 0], s1 = s[b * 3 + 1], s2 = s[b * 3 + 2];
        float ws = s0 * arrB[(tid + 511) & 511] + s1 * arrB[tid]
                 + s2 * arrB[(tid + 1) & 511];
        float p0 = exp2f(gamma * log2f(ws));      // ws > 0
        float psum = blockReduceSum(p0, scratch);
        float w0 = p0 / psum + 1e-16f;
        arrA[tid] = w0;
        out_w[b * NN + tid] = w0;
        __syncthreads();                   // publish w

        // ---- phase 3: read (smem for rows<256, L2 for rest) + erase/add .cs store ----
        const float4 e4 = *(const float4*)(e + b * UU + gl * 4);
        const float4 a4 = *(const float4*)(a + b * UU + gl * 4);
        float4 racc = make_float4(0.f, 0.f, 0.f, 0.f);
        #pragma unroll 4
        for (int i = 0; i < 16; ++i) {
            int row = gid + (i << 5);
            float4 m = (i < 8) ? *(const float4*)(tile + row * 64 + gl * 4)
                               : *(const float4*)(memb + row * 64 + gl * 4);
            float wn = arrA[row];
            racc.x += wn * m.x;
            racc.y += wn * m.y;
            racc.z += wn * m.z;
            racc.w += wn * m.w;
            float4 nm;
            nm.x = m.x * (1.f - wn * e4.x) + wn * a4.x;
            nm.y = m.y * (1.f - wn * e4.y) + wn * a4.y;
            nm.z = m.z * (1.f - wn * e4.z) + wn * a4.z;
            nm.w = m.w * (1.f - wn * e4.w) + wn * a4.w;
            stg_cs(outmb + row * 64 + gl * 4, nm);
        }

        // ---- r epilogue: 32 group-partials -> 8 -> 1 ----
        *(float4*)&rpart[gid * 64 + gl * 4] = racc;
        __syncthreads();
        {
            int col = tid & 63, h = tid >> 6;     // h = 0..7
            float sv = 0.f;
            #pragma unroll
            for (int r2 = 0; r2 < 4; ++r2) sv += rpart[(h * 4 + r2) * 64 + col];
            arrB[h * 64 + col] = sv;
        }
        __syncthreads();
        if (tid < UU) {
            float rs = 0.f;
            #pragma unroll
            for (int i2 = 0; i2 < 8; ++i2) rs += arrB[i2 * 64 + tid];
            out_r[b * UU + tid] = rs;
        }
        __syncthreads();                   // protect smem before next batch
    }
}

extern "C" void kernel_launch(void* const* d_in, const int* in_sizes, int n_in,
                              void* d_out, int out_size) {
    const float* memory = (const float*)d_in[0];
    const float* k      = (const float*)d_in[1];
    const float* beta   = (const float*)d_in[2];
    const float* g      = (const float*)d_in[3];
    const float* s      = (const float*)d_in[4];
    const float* gamma  = (const float*)d_in[5];
    const float* w_pre  = (const float*)d_in[6];
    const float* e      = (const float*)d_in[7];
    const float* a      = (const float*)d_in[8];

    float* out   = (float*)d_out;
    float* out_w = out;                               // (B, N)
    float* out_r = out_w + (long)BB * NN;             // (B, U)
    float* out_m = out_r + (long)BB * UU;             // (B, N, U)

    const int smem_bytes = SMEM_FLOATS * sizeof(float);
    cudaFuncSetAttribute(ntm_kernel,
                         cudaFuncAttributeMaxDynamicSharedMemorySize,
                         smem_bytes);

    ntm_kernel<<<NCTA, NT, smem_bytes>>>(memory, k, beta, g, s, gamma, w_pre, e, a,
                                         out_w, out_r, out_m);
}